// round 4
// baseline (speedup 1.0000x reference)
#include <cuda_runtime.h>

// RMAC: x (64, 2048, 16, 16) f32 -> out (64, 14*2048) f32, L2-normalized rows.
// Regions (14): l1 1x [0,16)^2 /256 ; l2 4x 10x10 at offsets {0,4} /100 ;
// l3 9x 8x8 at offsets {0,3,6} /64.  feat index = reg*2048 + c.

#define BATCH   64
#define CDIM    2048
#define FEAT    28672           // 14 * 2048
#define TILES   16              // (b,c) tiles per block

// 6 distinct 1-D windows (same set for rows and cols):
// 0:[0,16) 1:[0,10) 2:[4,14) 3:[0,8) 4:[3,11) 5:[6,14)
__constant__ int c_wstart[6] = {0, 0, 4, 0, 3, 6};
__constant__ int c_wlen[6]   = {16, 10, 10, 8, 8, 8};
// region -> (row window, col window, 1/area)
__constant__ int   c_rw[14]  = {0, 1,1,2,2, 3,3,3,4,4,4,5,5,5};
__constant__ int   c_cw[14]  = {0, 1,2,1,2, 3,4,5,3,4,5,3,4,5};
__constant__ float c_inv[14] = {1.0f/256.0f,
                                0.01f, 0.01f, 0.01f, 0.01f,
                                1.0f/64.0f, 1.0f/64.0f, 1.0f/64.0f,
                                1.0f/64.0f, 1.0f/64.0f, 1.0f/64.0f,
                                1.0f/64.0f, 1.0f/64.0f, 1.0f/64.0f};

__global__ __launch_bounds__(256)
void rmac_pool(const float* __restrict__ x, float* __restrict__ out) {
    // cs[tile][colwin][row], row-stride 17 to dodge bank conflicts
    __shared__ float cs[TILES][6][17];

    const int tid  = threadIdx.x;
    const int tile = tid >> 4;      // 0..15
    const int row  = tid & 15;      // 0..15

    const int gtile = blockIdx.x * TILES + tile;      // (b,c) tile index, < 131072
    const float* p = x + (size_t)gtile * 256 + row * 16;

    float4 v0 = __ldg((const float4*)(p + 0));
    float4 v1 = __ldg((const float4*)(p + 4));
    float4 v2 = __ldg((const float4*)(p + 8));
    float4 v3 = __ldg((const float4*)(p + 12));
    float r[16] = {v0.x, v0.y, v0.z, v0.w,
                   v1.x, v1.y, v1.z, v1.w,
                   v2.x, v2.y, v2.z, v2.w,
                   v3.x, v3.y, v3.z, v3.w};

    // 6 column-window sums for this row (direct sums, no cancellation)
    float s0_8  = ((r[0]+r[1])+(r[2]+r[3])) + ((r[4]+r[5])+(r[6]+r[7]));
    float s8_16 = ((r[8]+r[9])+(r[10]+r[11])) + ((r[12]+r[13])+(r[14]+r[15]));
    float sfull = s0_8 + s8_16;
    float s0_10 = s0_8 + (r[8] + r[9]);
    float s4_14 = ((r[4]+r[5])+(r[6]+r[7])) + ((r[8]+r[9])+(r[10]+r[11]))
                + (r[12] + r[13]);
    float s3_11 = ((r[3]+r[4])+(r[5]+r[6])) + ((r[7]+r[8])+(r[9]+r[10]));
    float s6_14 = ((r[6]+r[7])+(r[8]+r[9])) + ((r[10]+r[11])+(r[12]+r[13]));

    cs[tile][0][row] = sfull;
    cs[tile][1][row] = s0_10;
    cs[tile][2][row] = s4_14;
    cs[tile][3][row] = s0_8;
    cs[tile][4][row] = s3_11;
    cs[tile][5][row] = s6_14;

    __syncthreads();

    // 224 threads: one (region, tile) each; t fastest -> coalesced 64B stores
    if (tid < 224) {
        const int reg = tid >> 4;          // 0..13
        const int t   = tid & 15;          // tile within block
        const int rw  = c_rw[reg];
        const int cw  = c_cw[reg];
        const int st  = c_wstart[rw];
        const int len = c_wlen[rw];

        float s = 0.0f;
        #pragma unroll 4
        for (int i = 0; i < len; ++i) s += cs[t][cw][st + i];

        const int gt = blockIdx.x * TILES + t;
        const int b  = gt >> 11;           // / 2048
        const int c  = gt & 2047;
        out[(size_t)b * FEAT + reg * CDIM + c] = s * c_inv[reg];
    }
}

// One block per batch row: 1024 threads x 7 float4 = 28672 floats in registers.
__global__ __launch_bounds__(1024)
void rmac_norm(float* __restrict__ out) {
    float4* p = (float4*)(out + (size_t)blockIdx.x * FEAT);
    const int tid = threadIdx.x;

    float4 v[7];
    float ss = 0.0f;
    #pragma unroll
    for (int k = 0; k < 7; ++k) {
        v[k] = p[tid + k * 1024];
        ss += v[k].x * v[k].x + v[k].y * v[k].y
            + v[k].z * v[k].z + v[k].w * v[k].w;
    }

    // block reduce
    __shared__ float red[32];
    __shared__ float s_inv;
    #pragma unroll
    for (int o = 16; o > 0; o >>= 1)
        ss += __shfl_xor_sync(0xFFFFFFFFu, ss, o);
    const int lane = tid & 31, wid = tid >> 5;
    if (lane == 0) red[wid] = ss;
    __syncthreads();
    if (wid == 0) {
        float t = red[lane];
        #pragma unroll
        for (int o = 16; o > 0; o >>= 1)
            t += __shfl_xor_sync(0xFFFFFFFFu, t, o);
        if (lane == 0) {
            float n = sqrtf(t);
            s_inv = 1.0f / fmaxf(n, 1e-12f);
        }
    }
    __syncthreads();
    const float inv = s_inv;

    #pragma unroll
    for (int k = 0; k < 7; ++k) {
        v[k].x *= inv; v[k].y *= inv; v[k].z *= inv; v[k].w *= inv;
        p[tid + k * 1024] = v[k];
    }
}

extern "C" void kernel_launch(void* const* d_in, const int* in_sizes, int n_in,
                              void* d_out, int out_size) {
    const float* x = (const float*)d_in[0];
    float* out = (float*)d_out;

    // 64*2048 tiles / 16 per block = 8192 blocks
    rmac_pool<<<8192, 256>>>(x, out);
    rmac_norm<<<BATCH, 1024>>>(out);
}